// round 15
// baseline (speedup 1.0000x reference)
#include <cuda_runtime.h>
#include <math.h>
#include <stdint.h>

#define T_DIM 512
#define B_DIM 128
#define D_IN  128
#define H_DIM 512

// ---- geometry: 8 row-groups x 16 col-CTAs, 256 threads / 8 warps ----
#define GROUPS 8
#define CTAS_PER_GROUP 16
#define ROWS_PER_GROUP 16
#define COLS_PER_CTA 32

// ---- SMEM layout (floats) ----
#define BHI_OFF 0                  // Whh hi planes (read once into regs)
#define BLO_OFF 16384
#define RED_OFF 32768              // red[8][16][33]
#define RED_WSTRIDE 528
#define WIH_HI 36992               // W_ih planes: [16 kt][4 n][32 lane] float2
#define WIH_LO 41088
#define XSTG   45184               // x[t+1] stage: [16][132]
#define XPB    47296               // xp buffer: [2 parity][16][33]
#define SMEM_FLOATS 48352
#define RNN_SMEM_BYTES (SMEM_FLOATS * 4)   // 193408

#define FRAGA_FLOATS 8192

// ---------------- scratch (device globals: allocation-free) ----------------
__device__ __align__(16) float g_fragA_hi[2 * GROUPS * FRAGA_FLOATS];  // [par][grp][frag]
__device__ __align__(16) float g_fragA_lo[2 * GROUPS * FRAGA_FLOATS];
__device__ int g_flags[GROUPS * CTAS_PER_GROUP * 32];   // per-CTA epoch flags, 128B apart

// ---------------- helpers ----------------
__device__ __forceinline__ int ld_acq(const int* p) {
    int v;
    asm volatile("ld.global.acquire.gpu.b32 %0, [%1];" : "=r"(v) : "l"(p));
    return v;
}
__device__ __forceinline__ void st_rel(int* p, int v) {
    asm volatile("st.global.release.gpu.b32 [%0], %1;" :: "l"(p), "r"(v));
}
__device__ __forceinline__ float f2tf32f(float x) {
    uint32_t r;
    asm("cvt.rna.tf32.f32 %0, %1;" : "=r"(r) : "f"(x));
    return __uint_as_float(r);
}
__device__ __forceinline__ void mma_tf32(float* d, float a0, float a1,
                                         float a2, float a3,
                                         float b0, float b1) {
    asm volatile(
        "mma.sync.aligned.m16n8k8.row.col.f32.tf32.tf32.f32 "
        "{%0,%1,%2,%3}, {%4,%5,%6,%7}, {%8,%9}, {%0,%1,%2,%3};"
        : "+f"(d[0]), "+f"(d[1]), "+f"(d[2]), "+f"(d[3])
        : "r"(__float_as_uint(a0)), "r"(__float_as_uint(a1)),
          "r"(__float_as_uint(a2)), "r"(__float_as_uint(a3)),
          "r"(__float_as_uint(b0)), "r"(__float_as_uint(b1)));
}

// ---------------- fused RNN: R12 structure + B-hi plane pinned in registers --
// 128 CTAs x 256 thr. CTA = 16 rows x 32 cols. 8 warps k-split (8 kt each),
// 2-producer waits. Whh hi fragments live in 64 regs/thread for all 512 steps
// (loaded once); only the lo plane is re-read from SMEM per step.
__global__ __launch_bounds__(256, 1)
void rnn_fused_kernel(const float* __restrict__ x,
                      const float* __restrict__ Wih,
                      const float* __restrict__ bih,
                      const float* __restrict__ Whh,
                      const float* __restrict__ bhh,
                      float* __restrict__ out) {
    extern __shared__ float sm[];

    const int tid  = threadIdx.x;
    const int lane = tid & 31;
    const int wrp  = tid >> 5;           // 0..7
    const int gID  = lane >> 2;
    const int tig  = lane & 3;
    const int grp  = blockIdx.x >> 4;
    const int cCTA = blockIdx.x & 15;
    const int rowbase = grp * ROWS_PER_GROUP;
    const int colbase = cCTA * COLS_PER_CTA;

    // ---- build Whh fragment planes ----
#pragma unroll
    for (int i = 0; i < 32; i++) {
        int s      = i * 256 + tid;
        int lane_s = s & 31;
        int n_s    = (s >> 5) & 3;
        int kt_s   = s >> 7;
        int k0     = kt_s * 8 + (lane_s & 3);
        int cl     = n_s * 8 + (lane_s >> 2);
        float w0 = Whh[(size_t)(colbase + cl) * H_DIM + k0];
        float w1 = Whh[(size_t)(colbase + cl) * H_DIM + k0 + 4];
        float h0 = f2tf32f(w0), l0 = f2tf32f(w0 - h0);
        float h1 = f2tf32f(w1), l1 = f2tf32f(w1 - h1);
        *(float2*)&sm[BHI_OFF + s * 2] = make_float2(h0, h1);
        *(float2*)&sm[BLO_OFF + s * 2] = make_float2(l0, l1);
    }
    // ---- build W_ih fragment planes ----
#pragma unroll
    for (int i = 0; i < 8; i++) {
        int s      = i * 256 + tid;
        int lane_s = s & 31;
        int n_s    = (s >> 5) & 3;
        int kt_s   = s >> 7;
        int k0     = kt_s * 8 + (lane_s & 3);
        int cl     = n_s * 8 + (lane_s >> 2);
        float w0 = Wih[(size_t)(colbase + cl) * D_IN + k0];
        float w1 = Wih[(size_t)(colbase + cl) * D_IN + k0 + 4];
        float h0 = f2tf32f(w0), l0 = f2tf32f(w0 - h0);
        float h1 = f2tf32f(w1), l1 = f2tf32f(w1 - h1);
        *(float2*)&sm[WIH_HI + s * 2] = make_float2(h0, h1);
        *(float2*)&sm[WIH_LO + s * 2] = make_float2(l0, l1);
    }

    const int er = tid >> 5;
    const int ec = tid & 31;
    const float biasv = bhh[colbase + ec];
    float bi0 = 0.0f, bi1 = 0.0f;
    if (wrp < 4) {
        bi0 = bih[colbase + 8 * wrp + 2 * tig];
        bi1 = bih[colbase + 8 * wrp + 2 * tig + 1];
    }
    __syncthreads();

    const int ktbase = wrp * 8;

    // ---- pin B-hi fragments in registers: 8 kt x 4 n float2 = 64 regs ----
    float2 bhr[8][4];
#pragma unroll
    for (int kt = 0; kt < 8; kt++)
#pragma unroll
        for (int n = 0; n < 4; n++)
            bhr[kt][n] = *(const float2*)&sm[BHI_OFF + (((ktbase + kt) * 4 + n) * 32 + lane) * 2];

    float* const hlast = out + (size_t)T_DIM * B_DIM * H_DIM;

    const size_t ob1 = (size_t)(rowbase + er) * H_DIM + colbase + ec;
    const size_t ob2 = (size_t)(rowbase + er + 8) * H_DIM + colbase + ec;

    // producer fragment-store coordinates (validated R9)
    const int kc   = colbase + ec;
    const int kt_p = kc >> 3;
    const int ln_p = er * 4 + (kc & 3);
    const int j_p  = (kc & 4) ? 2 : 0;
    const size_t foff = (size_t)grp * FRAGA_FLOATS + (size_t)(kt_p * 32 + ln_p) * 4 + j_p;

    int* const myflag = &g_flags[(grp * CTAS_PER_GROUP + cCTA) * 32];
    int* const pf0 = &g_flags[(grp * CTAS_PER_GROUP + 2 * wrp) * 32];
    int* const pf1 = &g_flags[(grp * CTAS_PER_GROUP + 2 * wrp + 1) * 32];

    const size_t grpbase = (size_t)grp * FRAGA_FLOATS;

    // epoch base (all flags equal at every replay boundary)
    const int base = ld_acq(myflag);

    // ---- prologue: stage x[0], compute xp[0] into parity 0 ----
    {
        int f0 = tid, f1 = tid + 256;
        int r0 = f0 >> 5, c0 = f0 & 31;
        int r1 = f1 >> 5, c1 = f1 & 31;
        float4 v0 = *(const float4*)&x[((size_t)0 * B_DIM + rowbase + r0) * D_IN + c0 * 4];
        float4 v1 = *(const float4*)&x[((size_t)0 * B_DIM + rowbase + r1) * D_IN + c1 * 4];
        *(float4*)&sm[XSTG + r0 * 132 + c0 * 4] = v0;
        *(float4*)&sm[XSTG + r1 * 132 + c1 * 4] = v1;
    }
    __syncthreads();
    if (wrp < 4) {
        float cHH[4] = {0,0,0,0}, cHL[4] = {0,0,0,0}, cLH[4] = {0,0,0,0};
#pragma unroll
        for (int kt = 0; kt < 16; kt++) {
            float a0 = sm[XSTG + gID * 132 + kt * 8 + tig];
            float a1 = sm[XSTG + (gID + 8) * 132 + kt * 8 + tig];
            float a2 = sm[XSTG + gID * 132 + kt * 8 + tig + 4];
            float a3 = sm[XSTG + (gID + 8) * 132 + kt * 8 + tig + 4];
            float ah0 = f2tf32f(a0), al0 = f2tf32f(a0 - ah0);
            float ah1 = f2tf32f(a1), al1 = f2tf32f(a1 - ah1);
            float ah2 = f2tf32f(a2), al2 = f2tf32f(a2 - ah2);
            float ah3 = f2tf32f(a3), al3 = f2tf32f(a3 - ah3);
            float2 bh = *(const float2*)&sm[WIH_HI + ((kt * 4 + wrp) * 32 + lane) * 2];
            float2 bl = *(const float2*)&sm[WIH_LO + ((kt * 4 + wrp) * 32 + lane) * 2];
            mma_tf32(cHH, ah0, ah1, ah2, ah3, bh.x, bh.y);
            mma_tf32(cHL, ah0, ah1, ah2, ah3, bl.x, bl.y);
            mma_tf32(cLH, al0, al1, al2, al3, bh.x, bh.y);
        }
        float* xb = &sm[XPB + 0 * 528];
        int c = 8 * wrp + 2 * tig;
        xb[gID * 33 + c]           = cHH[0] + cHL[0] + cLH[0] + bi0;
        xb[gID * 33 + c + 1]       = cHH[1] + cHL[1] + cLH[1] + bi1;
        xb[(gID + 8) * 33 + c]     = cHH[2] + cHL[2] + cLH[2] + bi0;
        xb[(gID + 8) * 33 + c + 1] = cHH[3] + cHL[3] + cLH[3] + bi1;
    }

    for (int t = 0; t < T_DIM; ++t) {
        // ---- early: LDG x[t+1] ----
        float4 xr0, xr1;
        int xr0r = 0, xr0c = 0, xr1r = 0, xr1c = 0;
        if (t < T_DIM - 1) {
            int f0 = tid, f1 = tid + 256;
            xr0r = f0 >> 5; xr0c = f0 & 31;
            xr1r = f1 >> 5; xr1c = f1 & 31;
            xr0 = __ldcg((const float4*)&x[((size_t)(t + 1) * B_DIM + rowbase + xr0r) * D_IN + xr0c * 4]);
            xr1 = __ldcg((const float4*)&x[((size_t)(t + 1) * B_DIM + rowbase + xr1r) * D_IN + xr1c * 4]);
        }

        if (t > 0) {
            // ---- wait for this warp's two producers ----
            if (lane == 0) {
                while (ld_acq(pf0) < base + t) { __nanosleep(8); }
                while (ld_acq(pf1) < base + t) { __nanosleep(8); }
            }
            __syncwarp();

            // ---- A-frags straight from global ----
            const int par = (t - 1) & 1;
            const float4* baseH = (const float4*)(g_fragA_hi
                                 + (size_t)par * GROUPS * FRAGA_FLOATS + grpbase);
            const float4* baseL = (const float4*)(g_fragA_lo
                                 + (size_t)par * GROUPS * FRAGA_FLOATS + grpbase);
            float4 ah[8], al[8];
#pragma unroll
            for (int kt = 0; kt < 8; kt++)
                ah[kt] = __ldcg(baseH + (ktbase + kt) * 32 + lane);
#pragma unroll
            for (int kt = 0; kt < 8; kt++)
                al[kt] = __ldcg(baseL + (ktbase + kt) * 32 + lane);

            float accHH[4][4], accHL[4][4], accLH[4][4];
#pragma unroll
            for (int n = 0; n < 4; n++)
#pragma unroll
                for (int j = 0; j < 4; j++) {
                    accHH[n][j] = 0.0f; accHL[n][j] = 0.0f; accLH[n][j] = 0.0f;
                }
#pragma unroll
            for (int kt = 0; kt < 8; kt++) {
                const int ktg = ktbase + kt;
#pragma unroll
                for (int n = 0; n < 4; n++) {
                    // hi plane from registers; lo plane from SMEM
                    float2 bh = bhr[kt][n];
                    float2 bl = *(const float2*)&sm[BLO_OFF + ((ktg * 4 + n) * 32 + lane) * 2];
                    mma_tf32(accHH[n], ah[kt].x, ah[kt].y, ah[kt].z, ah[kt].w, bh.x, bh.y);
                    mma_tf32(accHL[n], ah[kt].x, ah[kt].y, ah[kt].z, ah[kt].w, bl.x, bl.y);
                    mma_tf32(accLH[n], al[kt].x, al[kt].y, al[kt].z, al[kt].w, bh.x, bh.y);
                }
            }

            float* rw = &sm[RED_OFF + wrp * RED_WSTRIDE];
#pragma unroll
            for (int n = 0; n < 4; n++) {
                float m0 = accHH[n][0] + accHL[n][0] + accLH[n][0];
                float m1 = accHH[n][1] + accHL[n][1] + accLH[n][1];
                float m2 = accHH[n][2] + accHL[n][2] + accLH[n][2];
                float m3 = accHH[n][3] + accHL[n][3] + accLH[n][3];
                const int c = n * 8 + 2 * tig;
                rw[gID * 33 + c]           = m0;
                rw[gID * 33 + c + 1]       = m1;
                rw[(gID + 8) * 33 + c]     = m2;
                rw[(gID + 8) * 33 + c + 1] = m3;
            }
        }
        __syncthreads();                 // SYNC1

        float s1 = 0.0f, s2 = 0.0f;
        if (t > 0) {
            const int rb1 = er * 33 + ec;
            const int rb2 = (er + 8) * 33 + ec;
#pragma unroll
            for (int w = 0; w < 8; w++) {
                s1 += sm[RED_OFF + w * RED_WSTRIDE + rb1];
                s2 += sm[RED_OFF + w * RED_WSTRIDE + rb2];
            }
        }
        const float xp1 = sm[XPB + (t & 1) * 528 + er * 33 + ec];
        const float xp2 = sm[XPB + (t & 1) * 528 + (er + 8) * 33 + ec];

        float v1 = tanhf(s1 + xp1 + biasv);
        float v2 = tanhf(s2 + xp2 + biasv);

        if (t < T_DIM - 1) {
            // frag split + store (critical path)
            const int par = t & 1;
            float h1 = f2tf32f(v1), l1 = f2tf32f(v1 - h1);
            float h2 = f2tf32f(v2), l2 = f2tf32f(v2 - h2);
            const size_t fb = (size_t)par * GROUPS * FRAGA_FLOATS + foff;
            *(float2*)&g_fragA_hi[fb] = make_float2(h1, h2);
            *(float2*)&g_fragA_lo[fb] = make_float2(l1, l2);

            // stage x[t+1]
            *(float4*)&sm[XSTG + xr0r * 132 + xr0c * 4] = xr0;
            *(float4*)&sm[XSTG + xr1r * 132 + xr1c * 4] = xr1;

            __syncthreads();             // SYNC2
            if (tid == 0) st_rel(myflag, base + t + 1);

            // off-path: xp[t+1] (warps 0..3)
            if (wrp < 4) {
                float cHH[4] = {0,0,0,0}, cHL[4] = {0,0,0,0}, cLH[4] = {0,0,0,0};
#pragma unroll
                for (int kt = 0; kt < 16; kt++) {
                    float a0 = sm[XSTG + gID * 132 + kt * 8 + tig];
                    float a1 = sm[XSTG + (gID + 8) * 132 + kt * 8 + tig];
                    float a2 = sm[XSTG + gID * 132 + kt * 8 + tig + 4];
                    float a3 = sm[XSTG + (gID + 8) * 132 + kt * 8 + tig + 4];
                    float ah0 = f2tf32f(a0), al0 = f2tf32f(a0 - ah0);
                    float ah1 = f2tf32f(a1), al1 = f2tf32f(a1 - ah1);
                    float ah2 = f2tf32f(a2), al2 = f2tf32f(a2 - ah2);
                    float ah3 = f2tf32f(a3), al3 = f2tf32f(a3 - ah3);
                    float2 bh = *(const float2*)&sm[WIH_HI + ((kt * 4 + wrp) * 32 + lane) * 2];
                    float2 bl = *(const float2*)&sm[WIH_LO + ((kt * 4 + wrp) * 32 + lane) * 2];
                    mma_tf32(cHH, ah0, ah1, ah2, ah3, bh.x, bh.y);
                    mma_tf32(cHL, ah0, ah1, ah2, ah3, bl.x, bl.y);
                    mma_tf32(cLH, al0, al1, al2, al3, bh.x, bh.y);
                }
                float* xb = &sm[XPB + ((t + 1) & 1) * 528];
                int c = 8 * wrp + 2 * tig;
                xb[gID * 33 + c]           = cHH[0] + cHL[0] + cLH[0] + bi0;
                xb[gID * 33 + c + 1]       = cHH[1] + cHL[1] + cLH[1] + bi1;
                xb[(gID + 8) * 33 + c]     = cHH[2] + cHL[2] + cLH[2] + bi0;
                xb[(gID + 8) * 33 + c + 1] = cHH[3] + cHL[3] + cLH[3] + bi1;
            }
        }

        // h_seq output stores (off the inter-CTA critical path)
        float* hout = out + (size_t)t * B_DIM * H_DIM;
        hout[ob1] = v1;
        hout[ob2] = v2;
        if (t == T_DIM - 1) { hlast[ob1] = v1; hlast[ob2] = v2; }
    }
}

// ---------------- launch ----------------
extern "C" void kernel_launch(void* const* d_in, const int* in_sizes, int n_in,
                              void* d_out, int out_size) {
    const float* x    = (const float*)d_in[0];
    const float* W_ih = (const float*)d_in[1];
    const float* b_ih = (const float*)d_in[2];
    const float* W_hh = (const float*)d_in[3];
    const float* b_hh = (const float*)d_in[4];
    float* out = (float*)d_out;

    cudaFuncSetAttribute(rnn_fused_kernel, cudaFuncAttributeMaxDynamicSharedMemorySize,
                         RNN_SMEM_BYTES);

    rnn_fused_kernel<<<128, 256, RNN_SMEM_BYTES>>>(x, W_ih, b_ih, W_hh, b_hh, out);
}